// round 2
// baseline (speedup 1.0000x reference)
#include <cuda_runtime.h>
#include <math.h>

// ---------------- problem constants ----------------
#define DXV   10000
#define DRV   5000
#define NANC  2000
#define NNODE 18000     // DXV + SPLIT*NANC
#define Dm    128
#define ECNT  200000
#define NBV   640       // B*V = 32*20
#define NCODE 80        // ND + NR
#define NDX   40
#define LBL   2000
#define MAXDEG 1024
#define MAXNNZ 512

// ---------------- scratch (no allocs allowed) ----------------
__device__ float g_classEmb[DXV * Dm];
__device__ float g_h[NNODE * Dm];
__device__ float g_el[NNODE];
__device__ float g_er[NNODE];
__device__ int   g_count[DXV];
__device__ int   g_rowoff[DXV + 1];
__device__ int   g_cursor[DXV];
__device__ int   g_eid[ECNT];
__device__ float g_dxALLonto[DXV * Dm];
__device__ float g_Sdx[DXV * Dm];
__device__ float g_Sdrug[DRV * Dm];
__device__ float g_visit[NBV * 2 * Dm];

// ---------------- reduce helpers ----------------
__device__ __forceinline__ float warpSum(float x) {
    #pragma unroll
    for (int o = 16; o; o >>= 1) x += __shfl_xor_sync(0xffffffffu, x, o);
    return x;
}
__device__ __forceinline__ float warpMax(float x) {
    #pragma unroll
    for (int o = 16; o; o >>= 1) x = fmaxf(x, __shfl_xor_sync(0xffffffffu, x, o));
    return x;
}
// 128-thread block reductions (sh must have >=4 floats)
__device__ __forceinline__ float blockSum128(float x, float* sh) {
    int w = threadIdx.x >> 5, l = threadIdx.x & 31;
    x = warpSum(x);
    if (l == 0) sh[w] = x;
    __syncthreads();
    float r = sh[0] + sh[1] + sh[2] + sh[3];
    __syncthreads();
    return r;
}
__device__ __forceinline__ float blockMax128(float x, float* sh) {
    int w = threadIdx.x >> 5, l = threadIdx.x & 31;
    x = warpMax(x);
    if (l == 0) sh[w] = x;
    __syncthreads();
    float r = fmaxf(fmaxf(sh[0], sh[1]), fmaxf(sh[2], sh[3]));
    __syncthreads();
    return r;
}

// ---------------- 1) classEmb = L2norm(sparse(dx2anc) @ S) ----------------
// one block (128 thr) per dx row; deterministic nonzero compaction in
// ancestor order (per-thread contiguous chunk + block scan).
__global__ void k_classEmb(const float* __restrict__ A, const float* __restrict__ S) {
    const int row = blockIdx.x, tid = threadIdx.x;
    const float* r = A + (long)row * NANC;

    // chunk of 16 ancestors per thread (128*16 = 2048 >= 2000; 2000%16==0)
    int   idxs[16];
    float vals[16];
    int cnt = 0;
    int a0 = tid * 16;
    if (a0 < NANC) {
        #pragma unroll
        for (int j = 0; j < 16; j++) {
            float v = r[a0 + j];
            if (v != 0.f) { vals[cnt] = v; idxs[cnt] = a0 + j; cnt++; }
        }
    }
    __shared__ int scnt[128];
    scnt[tid] = cnt;
    __syncthreads();
    for (int o = 1; o < 128; o <<= 1) {
        int t = (tid >= o) ? scnt[tid - o] : 0;
        __syncthreads();
        scnt[tid] += t;
        __syncthreads();
    }
    int excl = scnt[tid] - cnt;
    int total = scnt[127];

    __shared__ float sval[MAXNNZ];
    __shared__ short sidx[MAXNNZ];
    float acc = 0.f;
    if (total <= MAXNNZ) {
        for (int j = 0; j < cnt; j++) { sval[excl + j] = vals[j]; sidx[excl + j] = (short)idxs[j]; }
        __syncthreads();
        for (int j = 0; j < total; j++)
            acc += sval[j] * S[(int)sidx[j] * Dm + tid];
    } else { // statistically impossible fallback, kept for memory safety
        __syncthreads();
        for (int a = 0; a < NANC; a++) {
            float v = __ldg(r + a);
            if (v != 0.f) acc += v * S[a * Dm + tid];
        }
    }
    __shared__ float sh[4];
    float ss = blockSum128(acc * acc, sh);
    float outv = acc / (sqrtf(ss) + 1e-12f);
    g_classEmb[row * Dm + tid] = outv;
}

// ---------------- 2) h = nodes @ gat_W  (32 rows per block) ----------------
__global__ void k_h(const float* __restrict__ dxEmb, const float* __restrict__ extra,
                    const float* __restrict__ W) {
    __shared__ float sn[32 * Dm];
    const int r0 = blockIdx.x * 32, tid = threadIdx.x;
    for (int i = tid; i < 32 * Dm; i += 128) {
        int rr = i >> 7, c = i & 127;
        int row = r0 + rr;
        float v = 0.f;
        if (row < NNODE)
            v = (row < DXV) ? dxEmb[row * Dm + c] : extra[(row - DXV) * Dm + c];
        sn[i] = v;
    }
    __syncthreads();
    float acc[32];
    #pragma unroll
    for (int rr = 0; rr < 32; rr++) acc[rr] = 0.f;
    for (int k = 0; k < Dm; k++) {
        float w = W[k * Dm + tid];
        #pragma unroll
        for (int rr = 0; rr < 32; rr++) acc[rr] += sn[rr * Dm + k] * w;
    }
    #pragma unroll
    for (int rr = 0; rr < 32; rr++) {
        int row = r0 + rr;
        if (row < NNODE) g_h[(long)row * Dm + tid] = acc[rr];
    }
}

// ---------------- 3) el/er (warp per node) ----------------
__global__ void k_elr(const float* __restrict__ al, const float* __restrict__ ar) {
    int gw = (blockIdx.x * blockDim.x + threadIdx.x) >> 5;
    int lane = threadIdx.x & 31;
    if (gw >= NNODE) return;
    const float* hr = g_h + (long)gw * Dm;
    float a = 0.f, b = 0.f;
    #pragma unroll
    for (int q = 0; q < 4; q++) {
        int d = lane + 32 * q;
        float hv = hr[d];
        a += hv * al[d];
        b += hv * ar[d];
    }
    a = warpSum(a);
    b = warpSum(b);
    if (lane == 0) { g_el[gw] = a; g_er[gw] = b; }
}

// ---------------- 4) CSR build ----------------
__global__ void k_zero() {
    int i = blockIdx.x * blockDim.x + threadIdx.x;
    if (i < DXV) g_count[i] = 0;
}
__global__ void k_countEdges(const int* __restrict__ dst) {
    int i = blockIdx.x * blockDim.x + threadIdx.x;
    if (i < ECNT) {
        int d = dst[i];
        if (d < DXV) atomicAdd(&g_count[d], 1);
    }
}
__global__ void k_scan() {
    __shared__ int s[1024];
    int tid = threadIdx.x;
    int carry = 0;
    for (int t = 0; t < 10; t++) {
        int i = t * 1024 + tid;
        int v = (i < DXV) ? g_count[i] : 0;
        s[tid] = v;
        __syncthreads();
        for (int o = 1; o < 1024; o <<= 1) {
            int x = (tid >= o) ? s[tid - o] : 0;
            __syncthreads();
            s[tid] += x;
            __syncthreads();
        }
        int excl = carry + s[tid] - v;
        if (i < DXV) { g_rowoff[i] = excl; g_cursor[i] = excl; }
        carry += s[1023];
        __syncthreads();
    }
    if (tid == 0) g_rowoff[DXV] = carry;
}
__global__ void k_scatter(const int* __restrict__ dst) {
    int i = blockIdx.x * blockDim.x + threadIdx.x;
    if (i < ECNT) {
        int d = dst[i];
        if (d < DXV) {
            int p = atomicAdd(&g_cursor[d], 1);
            g_eid[p] = i;
        }
    }
}

// ---------------- 5) GAT aggregate per dst + fuse classEmb ----------------
__global__ void k_agg(const int* __restrict__ esrc) {
    const int d = blockIdx.x, tid = threadIdx.x;
    __shared__ int   sid[MAXDEG];
    __shared__ int   ssrc[MAXDEG];
    __shared__ float sw[MAXDEG];
    __shared__ float shred[4];

    int base = g_rowoff[d];
    int n = g_rowoff[d + 1] - base;
    if (n > MAXDEG) n = MAXDEG;

    for (int j = tid; j < n; j += 128) sid[j] = g_eid[base + j];
    __syncthreads();
    // deterministic: sort edge ids ascending via rank (ids unique)
    for (int j = tid; j < n; j += 128) {
        int id = sid[j];
        int rk = 0;
        for (int k = 0; k < n; k++) rk += (sid[k] < id);
        ssrc[rk] = id; // temp: sorted edge id
    }
    __syncthreads();
    float er_d = g_er[d];
    for (int j = tid; j < n; j += 128) {
        int e = ssrc[j];
        int s = esrc[e];
        float x = g_el[s] + er_d;
        sw[j] = (x >= 0.f) ? x : 0.2f * x;  // leaky_relu
        ssrc[j] = s;
    }
    __syncthreads();
    float m = -1e30f;
    for (int j = tid; j < n; j += 128) m = fmaxf(m, sw[j]);
    m = blockMax128(m, shred);
    float ps = 0.f;
    for (int j = tid; j < n; j += 128) {
        float w = __expf(sw[j] - m);
        sw[j] = w;
        ps += w;
    }
    float denom = blockSum128(ps, shred) + 1e-9f;
    __syncthreads();
    float acc = 0.f;
    for (int j = 0; j < n; j++)
        acc += sw[j] * g_h[(long)ssrc[j] * Dm + tid];
    g_dxALLonto[(long)d * Dm + tid] = acc / denom + g_classEmb[(long)d * Dm + tid];
}

// ---------------- 6) per-table score projections ----------------
// Sdx[i]   = dxEmb[i] @ attnW[0:128]   + dxALLonto[i] @ attnW[128:256]
// Sdrug[j] = drEmb[j] @ attnW[0:128]   + drEmb2[j]    @ attnW[128:256]
#define NDXB 313  // ceil(10000/32)
__global__ void k_scoretab(const float* __restrict__ dxEmb,
                           const float* __restrict__ drEmb,
                           const float* __restrict__ drEmb2,
                           const float* __restrict__ attnW) {
    __shared__ float sn[32 * 256];
    const int tid = threadIdx.x;
    const bool isdx = blockIdx.x < NDXB;
    const int r0 = isdx ? blockIdx.x * 32 : (blockIdx.x - NDXB) * 32;
    const int nrows = isdx ? DXV : DRV;
    const float* X1 = isdx ? dxEmb : drEmb;
    const float* X2 = isdx ? g_dxALLonto : drEmb2;
    float* out = isdx ? g_Sdx : g_Sdrug;

    for (int i = tid; i < 32 * 256; i += 128) {
        int rr = i >> 8, c = i & 255;
        int row = r0 + rr;
        float v = 0.f;
        if (row < nrows)
            v = (c < Dm) ? X1[(long)row * Dm + c] : X2[(long)row * Dm + (c - Dm)];
        sn[i] = v;
    }
    __syncthreads();
    float acc[32];
    #pragma unroll
    for (int rr = 0; rr < 32; rr++) acc[rr] = 0.f;
    for (int k = 0; k < 256; k++) {
        float w = attnW[k * Dm + tid];
        #pragma unroll
        for (int rr = 0; rr < 32; rr++) acc[rr] += sn[rr * 256 + k] * w;
    }
    #pragma unroll
    for (int rr = 0; rr < 32; rr++) {
        int row = r0 + rr;
        if (row < nrows) out[(long)row * Dm + tid] = acc[rr];
    }
}

// ---------------- 7) per-visit attention ----------------
__global__ void k_visit(const int* __restrict__ dxseqs, const int* __restrict__ drugseqs,
                        const float* __restrict__ dxEmb, const float* __restrict__ drEmb,
                        const float* __restrict__ drEmb2, const float* __restrict__ attnW,
                        const float* __restrict__ attnB, const float* __restrict__ combW,
                        const float* __restrict__ combB) {
    const int bv = blockIdx.x, tid = threadIdx.x;
    __shared__ int   sh_idx[NCODE];
    __shared__ float s_u[256];
    __shared__ float s_up[Dm];
    __shared__ float s_sc[NCODE];
    __shared__ float s_alpha[NCODE];
    __shared__ float shred[4];

    if (tid < NDX)            sh_idx[tid] = dxseqs[bv * NDX + tid];
    else if (tid < NCODE)     sh_idx[tid] = drugseqs[bv * NDX + (tid - NDX)];
    __syncthreads();

    // u = mean over codes
    float u0 = 0.f, u1 = 0.f;
    for (int k = 0; k < NCODE; k++) {
        int id = sh_idx[k];
        const float *p0, *p1;
        if (k < NDX) { p0 = dxEmb + (long)id * Dm; p1 = g_dxALLonto + (long)id * Dm; }
        else         { p0 = drEmb + (long)id * Dm; p1 = drEmb2 + (long)id * Dm; }
        u0 += p0[tid];
        u1 += p1[tid];
    }
    s_u[tid] = u0 * (1.f / NCODE);
    s_u[Dm + tid] = u1 * (1.f / NCODE);
    __syncthreads();

    // u_part = u @ attnW[256:512] + attn_b
    float up = attnB[tid];
    for (int k = 0; k < 256; k++)
        up += s_u[k] * attnW[(256 + k) * Dm + tid];
    s_up[tid] = up;
    __syncthreads();

    // scores: warp-per-code
    const int w = tid >> 5, lane = tid & 31;
    const float cb = combB[0];
    for (int k = w; k < NCODE; k += 4) {
        int id = sh_idx[k];
        const float* base = (k < NDX) ? (g_Sdx + (long)id * Dm) : (g_Sdrug + (long)id * Dm);
        float t = 0.f;
        #pragma unroll
        for (int q = 0; q < 4; q++) {
            int d = lane + 32 * q;
            float s = tanhf(base[d] + s_up[d]);
            t += s * combW[d];
        }
        t = warpSum(t);
        if (lane == 0) s_sc[k] = t + cb;
    }
    __syncthreads();

    // softmax over 80 codes
    float sv = (tid < NCODE) ? s_sc[tid] : -1e30f;
    float m = blockMax128(sv, shred);
    float e = (tid < NCODE) ? __expf(sv - m) : 0.f;
    float Z = blockSum128(e, shred);
    if (tid < NCODE) s_alpha[tid] = e / Z;
    __syncthreads();

    // visit = sum alpha_k * code_k
    float v0 = 0.f, v1 = 0.f;
    for (int k = 0; k < NCODE; k++) {
        float a = s_alpha[k];
        int id = sh_idx[k];
        const float *p0, *p1;
        if (k < NDX) { p0 = dxEmb + (long)id * Dm; p1 = g_dxALLonto + (long)id * Dm; }
        else         { p0 = drEmb + (long)id * Dm; p1 = drEmb2 + (long)id * Dm; }
        v0 += a * p0[tid];
        v1 += a * p1[tid];
    }
    g_visit[bv * 256 + tid] = v0;
    g_visit[bv * 256 + Dm + tid] = v1;
}

// ---------------- 8) out = sigmoid(visit @ dp_W + dp_b) ----------------
__global__ void k_dp(const float* __restrict__ dpW, const float* __restrict__ dpB,
                     float* __restrict__ out) {
    __shared__ float sv[32 * 256];
    const int tid = threadIdx.x;
    const int l = blockIdx.x * 128 + tid;
    const int r0 = blockIdx.y * 32;
    for (int i = tid; i < 32 * 256; i += 128)
        sv[i] = g_visit[r0 * 256 + i];
    __syncthreads();
    if (l >= LBL) return;
    float acc[32];
    #pragma unroll
    for (int rr = 0; rr < 32; rr++) acc[rr] = 0.f;
    for (int k = 0; k < 256; k++) {
        float w = dpW[k * LBL + l];
        #pragma unroll
        for (int rr = 0; rr < 32; rr++) acc[rr] += sv[rr * 256 + k] * w;
    }
    float b = dpB[l];
    #pragma unroll
    for (int rr = 0; rr < 32; rr++) {
        float x = acc[rr] + b;
        out[(long)(r0 + rr) * LBL + l] = 1.f / (1.f + __expf(-x));
    }
}

// ---------------- launcher ----------------
extern "C" void kernel_launch(void* const* d_in, const int* in_sizes, int n_in,
                              void* d_out, int out_size) {
    const int*   dxseqs  = (const int*)d_in[0];
    const int*   drugseqs= (const int*)d_in[1];
    const int*   esrc    = (const int*)d_in[2];
    const int*   edst    = (const int*)d_in[3];
    const float* dx2anc  = (const float*)d_in[4];
    const float* dxEmb   = (const float*)d_in[5];
    const float* drEmb   = (const float*)d_in[6];
    const float* drEmb2  = (const float*)d_in[7];
    const float* extra   = (const float*)d_in[8];
    const float* S       = (const float*)d_in[9];
    const float* gatW    = (const float*)d_in[10];
    const float* gal     = (const float*)d_in[11];
    const float* gar     = (const float*)d_in[12];
    const float* attnW   = (const float*)d_in[13];
    const float* attnB   = (const float*)d_in[14];
    const float* combW   = (const float*)d_in[15];
    const float* combB   = (const float*)d_in[16];
    const float* dpW     = (const float*)d_in[17];
    const float* dpB     = (const float*)d_in[18];
    float*       out     = (float*)d_out;

    k_classEmb<<<DXV, 128>>>(dx2anc, S);
    k_h<<<(NNODE + 31) / 32, 128>>>(dxEmb, extra, gatW);
    k_elr<<<(NNODE * 32 + 255) / 256, 256>>>(gal, gar);
    k_zero<<<(DXV + 255) / 256, 256>>>();
    k_countEdges<<<(ECNT + 255) / 256, 256>>>(edst);
    k_scan<<<1, 1024>>>();
    k_scatter<<<(ECNT + 255) / 256, 256>>>(edst);
    k_agg<<<DXV, 128>>>(esrc);
    k_scoretab<<<NDXB + (DRV + 31) / 32, 128>>>(dxEmb, drEmb, drEmb2, attnW);
    k_visit<<<NBV, 128>>>(dxseqs, drugseqs, dxEmb, drEmb, drEmb2,
                          attnW, attnB, combW, combB);
    k_dp<<<dim3((LBL + 127) / 128, NBV / 32), 128>>>(dpW, dpB, out);
}

// round 3
// speedup vs baseline: 1.3852x; 1.3852x over previous
#include <cuda_runtime.h>
#include <math.h>

// ---------------- problem constants ----------------
#define DXV   10000
#define DRV   5000
#define NANC  2000
#define NNODE 18000     // DXV + SPLIT*NANC
#define Dm    128
#define ECNT  200000
#define NBV   640       // B*V
#define NCODE 80
#define NDX   40
#define LBL   2000
#define MAXDEG 1024

#define H_TILES 563     // ceil(18000/32)
#define Z_BLOCKS 79     // ceil(10000/128)
#define NDXB 313        // ceil(10000/32)
#define NDRB 157        // ceil(5000/32)

// ---------------- scratch ----------------
__device__ float g_classEmb[DXV * Dm];
__device__ float g_h[NNODE * Dm];
__device__ float g_el[NNODE];
__device__ float g_er[NNODE];
__device__ int   g_count[DXV];
__device__ int   g_rowoff[DXV + 1];
__device__ int   g_rank[ECNT];
__device__ int   g_eid[ECNT];
__device__ float g_dxALLonto[DXV * Dm];
__device__ float g_Sdx[DXV * Dm];
__device__ float g_Sdrug[DRV * Dm];
__device__ float g_visit[NBV * 2 * Dm];

// ---------------- helpers ----------------
__device__ __forceinline__ float warpSum(float x) {
    #pragma unroll
    for (int o = 16; o; o >>= 1) x += __shfl_xor_sync(0xffffffffu, x, o);
    return x;
}
__device__ __forceinline__ float warpMax(float x) {
    #pragma unroll
    for (int o = 16; o; o >>= 1) x = fmaxf(x, __shfl_xor_sync(0xffffffffu, x, o));
    return x;
}
__device__ __forceinline__ float blockSum128(float x, float* sh) {
    int w = threadIdx.x >> 5, l = threadIdx.x & 31;
    x = warpSum(x);
    if (l == 0) sh[w] = x;
    __syncthreads();
    float r = sh[0] + sh[1] + sh[2] + sh[3];
    __syncthreads();
    return r;
}
__device__ __forceinline__ float blockMax128(float x, float* sh) {
    int w = threadIdx.x >> 5, l = threadIdx.x & 31;
    x = warpMax(x);
    if (l == 0) sh[w] = x;
    __syncthreads();
    float r = fmaxf(fmaxf(sh[0], sh[1]), fmaxf(sh[2], sh[3]));
    __syncthreads();
    return r;
}
__device__ __forceinline__ float fast_tanh(float x) {
    float y;
    asm("tanh.approx.f32 %0, %1;" : "=f"(y) : "f"(x));
    return y;
}

// =====================================================================
// L1 mega: classEmb rows | h+el/er tiles | zero counts
// =====================================================================
__global__ void k_mega1(const float* __restrict__ A, const float* __restrict__ S,
                        const float* __restrict__ dxEmb, const float* __restrict__ extra,
                        const float* __restrict__ W, const float* __restrict__ al,
                        const float* __restrict__ ar) {
    __shared__ __align__(16) char smem_raw[32 * Dm * 4 + 64];  // 16KB union + pad
    const int bid = blockIdx.x, tid = threadIdx.x;
    const int l = tid & 31, w = tid >> 5;

    if (bid < DXV) {
        // ---- classEmb: L2norm(sparse row @ S), ballot compaction ----
        float* sval = (float*)smem_raw;                 // [512]
        short* sidx = (short*)(sval + 512);             // [512]
        int*   scnt = (int*)(sidx + 512);               // [4]
        float* sred = (float*)(scnt + 8);               // [4]
        const float* r = A + (long)bid * NANC;
        int base = 0;
        #pragma unroll
        for (int t = 0; t < 16; t++) {
            int a = w * 512 + t * 32 + l;
            float v = (a < NANC) ? __ldg(r + a) : 0.f;
            bool nz = (v != 0.f);
            unsigned mask = __ballot_sync(0xffffffffu, nz);
            if (nz) {
                int p = base + __popc(mask & ((1u << l) - 1u));
                if (p < 128) { sval[w * 128 + p] = v; sidx[w * 128 + p] = (short)a; }
            }
            base += __popc(mask);
        }
        if (l == 0) scnt[w] = (base < 128) ? base : 128;
        __syncthreads();
        float acc = 0.f;
        for (int ww = 0; ww < 4; ww++) {
            int c = scnt[ww];
            #pragma unroll 2
            for (int j = 0; j < c; j++)
                acc += sval[ww * 128 + j] * __ldg(S + (int)sidx[ww * 128 + j] * Dm + tid);
        }
        float ss = blockSum128(acc * acc, sred);
        g_classEmb[(long)bid * Dm + tid] = acc / (sqrtf(ss) + 1e-12f);
    } else if (bid < DXV + H_TILES) {
        // ---- h = nodes @ gat_W (32 rows), fused el/er ----
        const int r0 = (bid - DXV) * 32;
        float4* sn4 = (float4*)smem_raw;                // [32*32]
        for (int i = tid; i < 32 * 32; i += 128) {
            int rr = i >> 5, c4 = i & 31;
            int row = r0 + rr;
            float4 v = make_float4(0.f, 0.f, 0.f, 0.f);
            if (row < NNODE)
                v = (row < DXV) ? ((const float4*)dxEmb)[row * 32 + c4]
                                : ((const float4*)extra)[(row - DXV) * 32 + c4];
            sn4[i] = v;
        }
        __syncthreads();
        float acc[32];
        #pragma unroll
        for (int rr = 0; rr < 32; rr++) acc[rr] = 0.f;
        for (int k = 0; k < Dm; k += 4) {
            float w0 = __ldg(W + (k + 0) * Dm + tid);
            float w1 = __ldg(W + (k + 1) * Dm + tid);
            float w2 = __ldg(W + (k + 2) * Dm + tid);
            float w3 = __ldg(W + (k + 3) * Dm + tid);
            #pragma unroll
            for (int rr = 0; rr < 32; rr++) {
                float4 x = sn4[rr * 32 + (k >> 2)];
                acc[rr] += x.x * w0 + x.y * w1 + x.z * w2 + x.w * w3;
            }
        }
        float a_t = __ldg(al + tid), b_t = __ldg(ar + tid);
        __syncthreads();  // done with sn4, reuse smem
        float* pel = (float*)smem_raw;        // [32*4]
        float* per = pel + 128;               // [32*4]
        #pragma unroll
        for (int rr = 0; rr < 32; rr++) {
            int row = r0 + rr;
            if (row < NNODE) g_h[(long)row * Dm + tid] = acc[rr];
            float ea = warpSum(acc[rr] * a_t);
            float eb = warpSum(acc[rr] * b_t);
            if (l == 0) { pel[rr * 4 + w] = ea; per[rr * 4 + w] = eb; }
        }
        __syncthreads();
        if (tid < 32) {
            int row = r0 + tid;
            if (row < NNODE)
                g_el[row] = pel[tid * 4] + pel[tid * 4 + 1] + pel[tid * 4 + 2] + pel[tid * 4 + 3];
        } else if (tid < 64) {
            int rr = tid - 32, row = r0 + rr;
            if (row < NNODE)
                g_er[row] = per[rr * 4] + per[rr * 4 + 1] + per[rr * 4 + 2] + per[rr * 4 + 3];
        }
    } else {
        int i = (bid - DXV - H_TILES) * 128 + tid;
        if (i < DXV) g_count[i] = 0;
    }
}

// =====================================================================
// L2: count incoming edges per dx dst + record per-edge rank
// =====================================================================
__global__ void k_count(const int* __restrict__ dst) {
    int i = blockIdx.x * blockDim.x + threadIdx.x;
    if (i < ECNT) {
        int d = dst[i];
        if (d < DXV) g_rank[i] = atomicAdd(&g_count[d], 1);
    }
}

// =====================================================================
// score-table tile: out[row] = X1[row]@attnW[0:128] + X2[row]@attnW[128:256]
// =====================================================================
__device__ __forceinline__ void scoretab_tile(int r0, int nrows,
                                              const float* __restrict__ X1,
                                              const float* __restrict__ X2,
                                              float* __restrict__ out,
                                              const float* __restrict__ attnW,
                                              float4* sn4 /* [32*64] */) {
    const int tid = threadIdx.x;
    for (int i = tid; i < 32 * 64; i += 128) {
        int rr = i >> 6, c4 = i & 63;
        int row = r0 + rr;
        float4 v = make_float4(0.f, 0.f, 0.f, 0.f);
        if (row < nrows)
            v = (c4 < 32) ? ((const float4*)X1)[row * 32 + c4]
                          : ((const float4*)X2)[row * 32 + (c4 - 32)];
        sn4[i] = v;
    }
    __syncthreads();
    float acc[32];
    #pragma unroll
    for (int rr = 0; rr < 32; rr++) acc[rr] = 0.f;
    for (int k = 0; k < 256; k += 4) {
        float w0 = __ldg(attnW + (k + 0) * Dm + tid);
        float w1 = __ldg(attnW + (k + 1) * Dm + tid);
        float w2 = __ldg(attnW + (k + 2) * Dm + tid);
        float w3 = __ldg(attnW + (k + 3) * Dm + tid);
        #pragma unroll
        for (int rr = 0; rr < 32; rr++) {
            float4 x = sn4[rr * 64 + (k >> 2)];
            acc[rr] += x.x * w0 + x.y * w1 + x.z * w2 + x.w * w3;
        }
    }
    #pragma unroll
    for (int rr = 0; rr < 32; rr++) {
        int row = r0 + rr;
        if (row < nrows) out[(long)row * Dm + tid] = acc[rr];
    }
}

// =====================================================================
// L3: block 0 = exclusive scan of counts; blocks 1.. = drug score table
// =====================================================================
__global__ void k_scanDrug(const float* __restrict__ drEmb, const float* __restrict__ drEmb2,
                           const float* __restrict__ attnW) {
    __shared__ __align__(16) float4 sn4[32 * 64];   // 32KB
    const int tid = threadIdx.x, l = tid & 31, w = tid >> 5;
    if (blockIdx.x == 0) {
        __shared__ int swarp[4];
        int carry = 0;
        for (int t = 0; t < Z_BLOCKS; t++) {
            int i = t * 128 + tid;
            int v = (i < DXV) ? g_count[i] : 0;
            int x = v;
            #pragma unroll
            for (int o = 1; o < 32; o <<= 1) {
                int y = __shfl_up_sync(0xffffffffu, x, o);
                if (l >= o) x += y;
            }
            if (l == 31) swarp[w] = x;
            __syncthreads();
            int wo = 0;
            #pragma unroll
            for (int q = 0; q < 4; q++) if (q < w) wo += swarp[q];
            if (i < DXV) g_rowoff[i] = carry + wo + x - v;
            carry += swarp[0] + swarp[1] + swarp[2] + swarp[3];
            __syncthreads();
        }
        if (tid == 0) g_rowoff[DXV] = carry;
    } else {
        int tile = blockIdx.x - 1;
        scoretab_tile(tile * 32, DRV, drEmb, drEmb2, g_Sdrug, attnW, sn4);
    }
}

// =====================================================================
// L4: atomic-free scatter using precomputed ranks
// =====================================================================
__global__ void k_scatter(const int* __restrict__ dst) {
    int i = blockIdx.x * blockDim.x + threadIdx.x;
    if (i < ECNT) {
        int d = dst[i];
        if (d < DXV) g_eid[g_rowoff[d] + g_rank[i]] = i;
    }
}

// =====================================================================
// L5: GAT softmax-aggregate per dst + fuse classEmb
// =====================================================================
__global__ void k_agg(const int* __restrict__ esrc) {
    const int d = blockIdx.x, tid = threadIdx.x;
    __shared__ int   sid[MAXDEG];
    __shared__ int   ssrc[MAXDEG];
    __shared__ float sw[MAXDEG];
    __shared__ float shred[4];

    int base = g_rowoff[d];
    int n = g_rowoff[d + 1] - base;
    if (n > MAXDEG) n = MAXDEG;

    for (int j = tid; j < n; j += 128) sid[j] = g_eid[base + j];
    __syncthreads();
    // deterministic ascending edge-id order via rank sort (ids unique, n small)
    for (int j = tid; j < n; j += 128) {
        int id = sid[j];
        int rk = 0;
        for (int k = 0; k < n; k++) rk += (sid[k] < id);
        ssrc[rk] = id;
    }
    __syncthreads();
    float er_d = g_er[d];
    for (int j = tid; j < n; j += 128) {
        int s = esrc[ssrc[j]];
        float x = g_el[s] + er_d;
        sw[j] = (x >= 0.f) ? x : 0.2f * x;
        ssrc[j] = s;
    }
    __syncthreads();
    float m = -1e30f;
    for (int j = tid; j < n; j += 128) m = fmaxf(m, sw[j]);
    m = blockMax128(m, shred);
    float ps = 0.f;
    for (int j = tid; j < n; j += 128) {
        float ww = __expf(sw[j] - m);
        sw[j] = ww;
        ps += ww;
    }
    float inv = 1.f / (blockSum128(ps, shred) + 1e-9f);
    __syncthreads();
    float acc = 0.f;
    #pragma unroll 4
    for (int j = 0; j < n; j++)
        acc += sw[j] * g_h[(long)ssrc[j] * Dm + tid];
    g_dxALLonto[(long)d * Dm + tid] = acc * inv + g_classEmb[(long)d * Dm + tid];
}

// =====================================================================
// L6: dx score table
// =====================================================================
__global__ void k_scoreDx(const float* __restrict__ dxEmb, const float* __restrict__ attnW) {
    __shared__ __align__(16) float4 sn4[32 * 64];
    scoretab_tile(blockIdx.x * 32, DXV, dxEmb, g_dxALLonto, g_Sdx, attnW, sn4);
}

// =====================================================================
// L7: per-visit attention
// =====================================================================
__global__ void k_visit(const int* __restrict__ dxseqs, const int* __restrict__ drugseqs,
                        const float* __restrict__ dxEmb, const float* __restrict__ drEmb,
                        const float* __restrict__ drEmb2, const float* __restrict__ attnW,
                        const float* __restrict__ attnB, const float* __restrict__ combW,
                        const float* __restrict__ combB) {
    const int bv = blockIdx.x, tid = threadIdx.x;
    __shared__ int   sh_idx[NCODE];
    __shared__ float s_u[256];
    __shared__ float s_up[Dm];
    __shared__ float s_sc[NCODE];
    __shared__ float s_alpha[NCODE];
    __shared__ float shred[4];

    if (tid < NDX)        sh_idx[tid] = dxseqs[bv * NDX + tid];
    else if (tid < NCODE) sh_idx[tid] = drugseqs[bv * NDX + (tid - NDX)];
    __syncthreads();

    float u0 = 0.f, u1 = 0.f;
    #pragma unroll 4
    for (int k = 0; k < NCODE; k++) {
        int id = sh_idx[k];
        const float *p0, *p1;
        if (k < NDX) { p0 = dxEmb + (long)id * Dm; p1 = g_dxALLonto + (long)id * Dm; }
        else         { p0 = drEmb + (long)id * Dm; p1 = drEmb2 + (long)id * Dm; }
        u0 += p0[tid];
        u1 += p1[tid];
    }
    s_u[tid] = u0 * (1.f / NCODE);
    s_u[Dm + tid] = u1 * (1.f / NCODE);
    __syncthreads();

    float up = __ldg(attnB + tid);
    #pragma unroll 4
    for (int k = 0; k < 256; k++)
        up += s_u[k] * __ldg(attnW + (256 + k) * Dm + tid);
    s_up[tid] = up;
    __syncthreads();

    const int w = tid >> 5, lane = tid & 31;
    const float cb = __ldg(combB);
    for (int k = w; k < NCODE; k += 4) {
        int id = sh_idx[k];
        const float* base = (k < NDX) ? (g_Sdx + (long)id * Dm) : (g_Sdrug + (long)id * Dm);
        float t = 0.f;
        #pragma unroll
        for (int q = 0; q < 4; q++) {
            int d = lane + 32 * q;
            t += fast_tanh(base[d] + s_up[d]) * __ldg(combW + d);
        }
        t = warpSum(t);
        if (lane == 0) s_sc[k] = t + cb;
    }
    __syncthreads();

    float sv = (tid < NCODE) ? s_sc[tid] : -1e30f;
    float m = blockMax128(sv, shred);
    float e = (tid < NCODE) ? __expf(sv - m) : 0.f;
    float Z = blockSum128(e, shred);
    if (tid < NCODE) s_alpha[tid] = e / Z;
    __syncthreads();

    float v0 = 0.f, v1 = 0.f;
    #pragma unroll 4
    for (int k = 0; k < NCODE; k++) {
        float a = s_alpha[k];
        int id = sh_idx[k];
        const float *p0, *p1;
        if (k < NDX) { p0 = dxEmb + (long)id * Dm; p1 = g_dxALLonto + (long)id * Dm; }
        else         { p0 = drEmb + (long)id * Dm; p1 = drEmb2 + (long)id * Dm; }
        v0 += a * p0[tid];
        v1 += a * p1[tid];
    }
    g_visit[bv * 256 + tid] = v0;
    g_visit[bv * 256 + Dm + tid] = v1;
}

// =====================================================================
// L8: out = sigmoid(visit @ dp_W + dp_b)
// =====================================================================
__global__ void k_dp(const float* __restrict__ dpW, const float* __restrict__ dpB,
                     float* __restrict__ out) {
    __shared__ __align__(16) float4 sv4[32 * 64];
    const int tid = threadIdx.x;
    const int l = blockIdx.x * 128 + tid;
    const int r0 = blockIdx.y * 32;
    for (int i = tid; i < 32 * 64; i += 128)
        sv4[i] = ((const float4*)g_visit)[r0 * 64 + i];
    __syncthreads();
    if (l >= LBL) return;
    float acc[32];
    #pragma unroll
    for (int rr = 0; rr < 32; rr++) acc[rr] = 0.f;
    for (int k = 0; k < 256; k += 4) {
        float w0 = __ldg(dpW + (k + 0) * LBL + l);
        float w1 = __ldg(dpW + (k + 1) * LBL + l);
        float w2 = __ldg(dpW + (k + 2) * LBL + l);
        float w3 = __ldg(dpW + (k + 3) * LBL + l);
        #pragma unroll
        for (int rr = 0; rr < 32; rr++) {
            float4 x = sv4[rr * 64 + (k >> 2)];
            acc[rr] += x.x * w0 + x.y * w1 + x.z * w2 + x.w * w3;
        }
    }
    float b = __ldg(dpB + l);
    #pragma unroll
    for (int rr = 0; rr < 32; rr++) {
        float x = acc[rr] + b;
        out[(long)(r0 + rr) * LBL + l] = 1.f / (1.f + __expf(-x));
    }
}

// ---------------- launcher ----------------
extern "C" void kernel_launch(void* const* d_in, const int* in_sizes, int n_in,
                              void* d_out, int out_size) {
    const int*   dxseqs  = (const int*)d_in[0];
    const int*   drugseqs= (const int*)d_in[1];
    const int*   esrc    = (const int*)d_in[2];
    const int*   edst    = (const int*)d_in[3];
    const float* dx2anc  = (const float*)d_in[4];
    const float* dxEmb   = (const float*)d_in[5];
    const float* drEmb   = (const float*)d_in[6];
    const float* drEmb2  = (const float*)d_in[7];
    const float* extra   = (const float*)d_in[8];
    const float* S       = (const float*)d_in[9];
    const float* gatW    = (const float*)d_in[10];
    const float* gal     = (const float*)d_in[11];
    const float* gar     = (const float*)d_in[12];
    const float* attnW   = (const float*)d_in[13];
    const float* attnB   = (const float*)d_in[14];
    const float* combW   = (const float*)d_in[15];
    const float* combB   = (const float*)d_in[16];
    const float* dpW     = (const float*)d_in[17];
    const float* dpB     = (const float*)d_in[18];
    float*       out     = (float*)d_out;

    k_mega1<<<DXV + H_TILES + Z_BLOCKS, 128>>>(dx2anc, S, dxEmb, extra, gatW, gal, gar);
    k_count<<<(ECNT + 255) / 256, 256>>>(edst);
    k_scanDrug<<<1 + NDRB, 128>>>(drEmb, drEmb2, attnW);
    k_scatter<<<(ECNT + 255) / 256, 256>>>(edst);
    k_agg<<<DXV, 128>>>(esrc);
    k_scoreDx<<<NDXB, 128>>>(dxEmb, attnW);
    k_visit<<<NBV, 128>>>(dxseqs, drugseqs, dxEmb, drEmb, drEmb2,
                          attnW, attnB, combW, combB);
    k_dp<<<dim3((LBL + 127) / 128, NBV / 32), 128>>>(dpW, dpB, out);
}

// round 5
// speedup vs baseline: 1.7035x; 1.2298x over previous
#include <cuda_runtime.h>
#include <math.h>

// ---------------- problem constants ----------------
#define DXV   10000
#define DRV   5000
#define NANC  2000
#define NNODE 18000     // DXV + SPLIT*NANC
#define Dm    128
#define ECNT  200000
#define NBV   640       // B*V
#define NCODE 80
#define NDX   40
#define LBL   2000
#define MAXDEG 192

#define H_TILES 563     // ceil(18000/32)
#define Z_BLOCKS 79     // ceil(10000/128)
#define NDXB 313        // ceil(10000/32)
#define NDRB 157        // ceil(5000/32)

typedef unsigned long long ULL;

// ---------------- scratch ----------------
__device__ float g_classEmb[DXV * Dm];
__device__ float g_h[NNODE * Dm];
__device__ float g_el[NNODE];
__device__ float g_er[NNODE];
__device__ int   g_count[DXV];
__device__ int   g_rowoff[DXV + 1];
__device__ int   g_rank[ECNT];
__device__ int   g_eid[ECNT];
__device__ float g_dxALLonto[DXV * Dm];
__device__ float g_Sdx[DXV * Dm];
__device__ float g_Sdrug[DRV * Dm];
__device__ float g_visit[NBV * 2 * Dm];

// ---------------- helpers ----------------
__device__ __forceinline__ float warpSum(float x) {
    #pragma unroll
    for (int o = 16; o; o >>= 1) x += __shfl_xor_sync(0xffffffffu, x, o);
    return x;
}
__device__ __forceinline__ float warpMax(float x) {
    #pragma unroll
    for (int o = 16; o; o >>= 1) x = fmaxf(x, __shfl_xor_sync(0xffffffffu, x, o));
    return x;
}
__device__ __forceinline__ float blockSum128(float x, float* sh) {
    int w = threadIdx.x >> 5, l = threadIdx.x & 31;
    x = warpSum(x);
    if (l == 0) sh[w] = x;
    __syncthreads();
    float r = sh[0] + sh[1] + sh[2] + sh[3];
    __syncthreads();
    return r;
}
__device__ __forceinline__ float blockMax128(float x, float* sh) {
    int w = threadIdx.x >> 5, l = threadIdx.x & 31;
    x = warpMax(x);
    if (l == 0) sh[w] = x;
    __syncthreads();
    float r = fmaxf(fmaxf(sh[0], sh[1]), fmaxf(sh[2], sh[3]));
    __syncthreads();
    return r;
}
__device__ __forceinline__ float fast_tanh(float x) {
    float y;
    asm("tanh.approx.f32 %0, %1;" : "=f"(y) : "f"(x));
    return y;
}
// packed fp32x2 FMA (FFMA2) — 2x fp32 math throughput, PTX-only
__device__ __forceinline__ ULL pk2(float lo, float hi) {
    ULL r; asm("mov.b64 %0, {%1, %2};" : "=l"(r) : "f"(lo), "f"(hi)); return r;
}
__device__ __forceinline__ void ffma2(ULL& d, ULL a, ULL b) {
    asm("fma.rn.f32x2 %0, %1, %2, %0;" : "+l"(d) : "l"(a), "l"(b));
}
__device__ __forceinline__ float fold2(ULL a) {
    float lo, hi; asm("mov.b64 {%0, %1}, %2;" : "=f"(lo), "=f"(hi) : "l"(a));
    return lo + hi;
}

// 32-row x 128-col GEMM tile core. sn: row-major float4 tile viewed as
// ulonglong2 (sn[r*K4 + k4] = X[row r][4k..4k+3]); even-k products in lo
// lane, odd-k in hi lane, folded at the end.
template<int K4, class F>
__device__ __forceinline__ void gemm32(const ulonglong2* __restrict__ sn,
                                       const float* __restrict__ wcol, int wstride,
                                       F emit) {
    ULL acc[32];
    #pragma unroll
    for (int r = 0; r < 32; r++) acc[r] = 0ull;
    #pragma unroll 2
    for (int k4 = 0; k4 < K4; k4++) {
        const float* wp = wcol + (k4 * 4) * wstride;
        ULL w01 = pk2(__ldg(wp), __ldg(wp + wstride));
        ULL w23 = pk2(__ldg(wp + 2 * wstride), __ldg(wp + 3 * wstride));
        #pragma unroll
        for (int r = 0; r < 32; r++) {
            ulonglong2 x = sn[r * K4 + k4];
            ffma2(acc[r], x.x, w01);
            ffma2(acc[r], x.y, w23);
        }
    }
    #pragma unroll
    for (int r = 0; r < 32; r++) emit(r, fold2(acc[r]));
}

// =====================================================================
// L0: classEmb = L2norm(sparse(dx2anc row) @ S)   (one block per row)
// =====================================================================
__global__ void k_classEmb(const float* __restrict__ A, const float* __restrict__ S) {
    const int row = blockIdx.x, tid = threadIdx.x;
    const int l = tid & 31, w = tid >> 5;
    __shared__ float sval[512];
    __shared__ short sidx[512];
    __shared__ int   scnt[4];
    __shared__ float sred[4];
    const float* r = A + (long)row * NANC;
    int base = 0;
    #pragma unroll
    for (int t = 0; t < 16; t++) {
        int a = w * 512 + t * 32 + l;
        float v = (a < NANC) ? __ldg(r + a) : 0.f;
        bool nz = (v != 0.f);
        unsigned mask = __ballot_sync(0xffffffffu, nz);
        if (nz) {
            int p = base + __popc(mask & ((1u << l) - 1u));
            if (p < 128) { sval[w * 128 + p] = v; sidx[w * 128 + p] = (short)a; }
        }
        base += __popc(mask);
    }
    if (l == 0) scnt[w] = (base < 128) ? base : 128;
    __syncthreads();
    float acc = 0.f;
    for (int ww = 0; ww < 4; ww++) {
        int c = scnt[ww];
        #pragma unroll 2
        for (int j = 0; j < c; j++)
            acc += sval[ww * 128 + j] * __ldg(S + (int)sidx[ww * 128 + j] * Dm + tid);
    }
    float ss = blockSum128(acc * acc, sred);
    g_classEmb[(long)row * Dm + tid] = acc / (sqrtf(ss) + 1e-12f);
}

// =====================================================================
// L1: h = nodes @ gat_W (32-row tiles) + fused el/er  |  zero counts
// =====================================================================
__global__ void k_hTiles(const float* __restrict__ dxEmb, const float* __restrict__ extra,
                         const float* __restrict__ W, const float* __restrict__ al,
                         const float* __restrict__ ar) {
    __shared__ __align__(16) char smem_raw[32 * Dm * 4];  // 16KB
    const int bid = blockIdx.x, tid = threadIdx.x;
    const int l = tid & 31, w = tid >> 5;

    if (bid >= H_TILES) {
        int i = (bid - H_TILES) * 128 + tid;
        if (i < DXV) g_count[i] = 0;
        return;
    }
    const int r0 = bid * 32;
    float4* sn4 = (float4*)smem_raw;   // [32*32] row-major
    for (int i = tid; i < 32 * 32; i += 128) {
        int rr = i >> 5, c4 = i & 31;
        int row = r0 + rr;
        float4 v = make_float4(0.f, 0.f, 0.f, 0.f);
        if (row < NNODE)
            v = (row < DXV) ? ((const float4*)dxEmb)[row * 32 + c4]
                            : ((const float4*)extra)[(row - DXV) * 32 + c4];
        sn4[i] = v;
    }
    __syncthreads();

    float a_t = __ldg(al + tid), b_t = __ldg(ar + tid);
    __shared__ float pel[32 * 4];
    __shared__ float per[32 * 4];
    gemm32<32>((const ulonglong2*)smem_raw, W + tid, Dm,
        [&](int rr, float hv) {
            int row = r0 + rr;
            if (row < NNODE) g_h[(long)row * Dm + tid] = hv;
            float ea = warpSum(hv * a_t);
            float eb = warpSum(hv * b_t);
            if (l == 0) { pel[rr * 4 + w] = ea; per[rr * 4 + w] = eb; }
        });
    __syncthreads();
    if (tid < 32) {
        int row = r0 + tid;
        if (row < NNODE)
            g_el[row] = pel[tid * 4] + pel[tid * 4 + 1] + pel[tid * 4 + 2] + pel[tid * 4 + 3];
    } else if (tid < 64) {
        int rr = tid - 32, row = r0 + rr;
        if (row < NNODE)
            g_er[row] = per[rr * 4] + per[rr * 4 + 1] + per[rr * 4 + 2] + per[rr * 4 + 3];
    }
}

// =====================================================================
// L2: count incoming edges per dx dst + record per-edge rank
// =====================================================================
__global__ void k_count(const int* __restrict__ dst) {
    int i = blockIdx.x * blockDim.x + threadIdx.x;
    if (i < ECNT) {
        int d = dst[i];
        if (d < DXV) g_rank[i] = atomicAdd(&g_count[d], 1);
    }
}

// =====================================================================
// score-table tile (K=256): out = X1@W[0:128] + X2@W[128:256]
// =====================================================================
__device__ __forceinline__ void scoretab_tile(int r0, int nrows,
                                              const float* __restrict__ X1,
                                              const float* __restrict__ X2,
                                              float* __restrict__ out,
                                              const float* __restrict__ attnW,
                                              float4* sn4 /* [32*64] */) {
    const int tid = threadIdx.x;
    for (int i = tid; i < 32 * 64; i += 128) {
        int rr = i >> 6, c4 = i & 63;
        int row = r0 + rr;
        float4 v = make_float4(0.f, 0.f, 0.f, 0.f);
        if (row < nrows)
            v = (c4 < 32) ? ((const float4*)X1)[row * 32 + c4]
                          : ((const float4*)X2)[row * 32 + (c4 - 32)];
        sn4[i] = v;
    }
    __syncthreads();
    gemm32<64>((const ulonglong2*)sn4, attnW + tid, Dm,
        [&](int rr, float v) {
            int row = r0 + rr;
            if (row < nrows) out[(long)row * Dm + tid] = v;
        });
}

// =====================================================================
// L3: block 0 = exclusive scan of counts; blocks 1.. = drug score table
// =====================================================================
__global__ void k_scanDrug(const float* __restrict__ drEmb, const float* __restrict__ drEmb2,
                           const float* __restrict__ attnW) {
    __shared__ __align__(16) float4 sn4[32 * 64];   // 32KB
    const int tid = threadIdx.x, l = tid & 31, w = tid >> 5;
    if (blockIdx.x == 0) {
        int* swarp = (int*)sn4;
        int carry = 0;
        for (int t = 0; t < Z_BLOCKS; t++) {
            int i = t * 128 + tid;
            int v = (i < DXV) ? g_count[i] : 0;
            int x = v;
            #pragma unroll
            for (int o = 1; o < 32; o <<= 1) {
                int y = __shfl_up_sync(0xffffffffu, x, o);
                if (l >= o) x += y;
            }
            if (l == 31) swarp[w] = x;
            __syncthreads();
            int wo = 0;
            #pragma unroll
            for (int q = 0; q < 4; q++) if (q < w) wo += swarp[q];
            if (i < DXV) g_rowoff[i] = carry + wo + x - v;
            carry += swarp[0] + swarp[1] + swarp[2] + swarp[3];
            __syncthreads();
        }
        if (tid == 0) g_rowoff[DXV] = carry;
    } else {
        scoretab_tile((blockIdx.x - 1) * 32, DRV, drEmb, drEmb2, g_Sdrug, attnW, sn4);
    }
}

// =====================================================================
// L4: atomic-free scatter using precomputed ranks
// =====================================================================
__global__ void k_scatter(const int* __restrict__ dst) {
    int i = blockIdx.x * blockDim.x + threadIdx.x;
    if (i < ECNT) {
        int d = dst[i];
        if (d < DXV) g_eid[g_rowoff[d] + g_rank[i]] = i;
    }
}

// =====================================================================
// L5: GAT softmax-aggregate per dst + fuse classEmb
// =====================================================================
__global__ void k_agg(const int* __restrict__ esrc) {
    const int d = blockIdx.x, tid = threadIdx.x;
    __shared__ int   sid[MAXDEG];
    __shared__ int   ssrc[MAXDEG];
    __shared__ float sw[MAXDEG];
    __shared__ float shred[4];

    int base = g_rowoff[d];
    int n = g_rowoff[d + 1] - base;
    if (n > MAXDEG) n = MAXDEG;

    for (int j = tid; j < n; j += 128) sid[j] = g_eid[base + j];
    __syncthreads();
    // deterministic ascending edge-id order via rank sort (ids unique, n small)
    for (int j = tid; j < n; j += 128) {
        int id = sid[j];
        int rk = 0;
        for (int k = 0; k < n; k++) rk += (sid[k] < id);
        ssrc[rk] = id;
    }
    __syncthreads();
    float er_d = g_er[d];
    for (int j = tid; j < n; j += 128) {
        int s = esrc[ssrc[j]];
        float x = g_el[s] + er_d;
        sw[j] = (x >= 0.f) ? x : 0.2f * x;
        ssrc[j] = s;
    }
    __syncthreads();
    float m = -1e30f;
    for (int j = tid; j < n; j += 128) m = fmaxf(m, sw[j]);
    m = blockMax128(m, shred);
    float ps = 0.f;
    for (int j = tid; j < n; j += 128) {
        float ww = __expf(sw[j] - m);
        sw[j] = ww;
        ps += ww;
    }
    float inv = 1.f / (blockSum128(ps, shred) + 1e-9f);
    __syncthreads();
    float acc = 0.f;
    #pragma unroll 4
    for (int j = 0; j < n; j++)
        acc += sw[j] * g_h[(long)ssrc[j] * Dm + tid];
    g_dxALLonto[(long)d * Dm + tid] = acc * inv + g_classEmb[(long)d * Dm + tid];
}

// =====================================================================
// L6: dx score table
// =====================================================================
__global__ void k_scoreDx(const float* __restrict__ dxEmb, const float* __restrict__ attnW) {
    __shared__ __align__(16) float4 sn4[32 * 64];
    scoretab_tile(blockIdx.x * 32, DXV, dxEmb, g_dxALLonto, g_Sdx, attnW, sn4);
}

// =====================================================================
// L7: per-visit attention
// =====================================================================
__global__ void k_visit(const int* __restrict__ dxseqs, const int* __restrict__ drugseqs,
                        const float* __restrict__ dxEmb, const float* __restrict__ drEmb,
                        const float* __restrict__ drEmb2, const float* __restrict__ attnW,
                        const float* __restrict__ attnB, const float* __restrict__ combW,
                        const float* __restrict__ combB) {
    const int bv = blockIdx.x, tid = threadIdx.x;
    __shared__ int   sh_idx[NCODE];
    __shared__ __align__(16) float s_u[256];
    __shared__ float s_up[Dm];
    __shared__ float s_sc[NCODE];
    __shared__ float s_alpha[NCODE];
    __shared__ float shred[4];

    if (tid < NDX)        sh_idx[tid] = dxseqs[bv * NDX + tid];
    else if (tid < NCODE) sh_idx[tid] = drugseqs[bv * NDX + (tid - NDX)];
    __syncthreads();

    float u0 = 0.f, u1 = 0.f;
    #pragma unroll 4
    for (int k = 0; k < NCODE; k++) {
        int id = sh_idx[k];
        const float *p0, *p1;
        if (k < NDX) { p0 = dxEmb + (long)id * Dm; p1 = g_dxALLonto + (long)id * Dm; }
        else         { p0 = drEmb + (long)id * Dm; p1 = drEmb2 + (long)id * Dm; }
        u0 += p0[tid];
        u1 += p1[tid];
    }
    s_u[tid] = u0 * (1.f / NCODE);
    s_u[Dm + tid] = u1 * (1.f / NCODE);
    __syncthreads();

    // u_part = u @ attnW[256:512] + attn_b   (k-paired FFMA2)
    {
        const ULL* su64 = (const ULL*)s_u;
        ULL up2 = 0ull;
        #pragma unroll 4
        for (int k2 = 0; k2 < 128; k2++) {
            ULL wv = pk2(__ldg(attnW + (256 + 2 * k2) * Dm + tid),
                         __ldg(attnW + (257 + 2 * k2) * Dm + tid));
            ffma2(up2, su64[k2], wv);
        }
        s_up[tid] = __ldg(attnB + tid) + fold2(up2);
    }
    __syncthreads();

    const int w = tid >> 5, lane = tid & 31;
    const float cb = __ldg(combB);
    for (int k = w; k < NCODE; k += 4) {
        int id = sh_idx[k];
        const float* base = (k < NDX) ? (g_Sdx + (long)id * Dm) : (g_Sdrug + (long)id * Dm);
        float t = 0.f;
        #pragma unroll
        for (int q = 0; q < 4; q++) {
            int d = lane + 32 * q;
            t += fast_tanh(base[d] + s_up[d]) * __ldg(combW + d);
        }
        t = warpSum(t);
        if (lane == 0) s_sc[k] = t + cb;
    }
    __syncthreads();

    float sv = (tid < NCODE) ? s_sc[tid] : -1e30f;
    float m = blockMax128(sv, shred);
    float e = (tid < NCODE) ? __expf(sv - m) : 0.f;
    float Z = blockSum128(e, shred);
    if (tid < NCODE) s_alpha[tid] = e / Z;
    __syncthreads();

    float v0 = 0.f, v1 = 0.f;
    #pragma unroll 4
    for (int k = 0; k < NCODE; k++) {
        float a = s_alpha[k];
        int id = sh_idx[k];
        const float *p0, *p1;
        if (k < NDX) { p0 = dxEmb + (long)id * Dm; p1 = g_dxALLonto + (long)id * Dm; }
        else         { p0 = drEmb + (long)id * Dm; p1 = drEmb2 + (long)id * Dm; }
        v0 += a * p0[tid];
        v1 += a * p1[tid];
    }
    g_visit[bv * 256 + tid] = v0;
    g_visit[bv * 256 + Dm + tid] = v1;
}

// =====================================================================
// L8: out = sigmoid(visit @ dp_W + dp_b)
// =====================================================================
__global__ void k_dp(const float* __restrict__ dpW, const float* __restrict__ dpB,
                     float* __restrict__ out) {
    __shared__ __align__(16) float4 sv4[32 * 64];
    const int tid = threadIdx.x;
    const int l = blockIdx.x * 128 + tid;
    const int r0 = blockIdx.y * 32;
    for (int i = tid; i < 32 * 64; i += 128)
        sv4[i] = ((const float4*)g_visit)[r0 * 64 + i];
    __syncthreads();
    if (l >= LBL) return;
    float b = __ldg(dpB + l);
    gemm32<64>((const ulonglong2*)sv4, dpW + l, LBL,
        [&](int rr, float v) {
            float x = v + b;
            out[(long)(r0 + rr) * LBL + l] = 1.f / (1.f + __expf(-x));
        });
}

// ---------------- launcher ----------------
extern "C" void kernel_launch(void* const* d_in, const int* in_sizes, int n_in,
                              void* d_out, int out_size) {
    const int*   dxseqs  = (const int*)d_in[0];
    const int*   drugseqs= (const int*)d_in[1];
    const int*   esrc    = (const int*)d_in[2];
    const int*   edst    = (const int*)d_in[3];
    const float* dx2anc  = (const float*)d_in[4];
    const float* dxEmb   = (const float*)d_in[5];
    const float* drEmb   = (const float*)d_in[6];
    const float* drEmb2  = (const float*)d_in[7];
    const float* extra   = (const float*)d_in[8];
    const float* S       = (const float*)d_in[9];
    const float* gatW    = (const float*)d_in[10];
    const float* gal     = (const float*)d_in[11];
    const float* gar     = (const float*)d_in[12];
    const float* attnW   = (const float*)d_in[13];
    const float* attnB   = (const float*)d_in[14];
    const float* combW   = (const float*)d_in[15];
    const float* combB   = (const float*)d_in[16];
    const float* dpW     = (const float*)d_in[17];
    const float* dpB     = (const float*)d_in[18];
    float*       out     = (float*)d_out;

    k_classEmb<<<DXV, 128>>>(dx2anc, S);
    k_hTiles<<<H_TILES + Z_BLOCKS, 128>>>(dxEmb, extra, gatW, gal, gar);
    k_count<<<(ECNT + 255) / 256, 256>>>(edst);
    k_scanDrug<<<1 + NDRB, 128>>>(drEmb, drEmb2, attnW);
    k_scatter<<<(ECNT + 255) / 256, 256>>>(edst);
    k_agg<<<DXV, 128>>>(esrc);
    k_scoreDx<<<NDXB, 128>>>(dxEmb, attnW);
    k_visit<<<NBV, 128>>>(dxseqs, drugseqs, dxEmb, drEmb, drEmb2,
                          attnW, attnB, combW, combB);
    k_dp<<<dim3((LBL + 127) / 128, NBV / 32), 128>>>(dpW, dpB, out);
}